// round 12
// baseline (speedup 1.0000x reference)
#include <cuda_runtime.h>
#include <math.h>

#define BATCH     64
#define NGT       32
#define NTOT      64512
#define NGROUPS   192    // 3 scales * 64 images
#define MBLOCKS   5376   // 84 * 64 match blocks
#define NT        256

// ---- scratch (no allocations allowed); all state self-resets each run ----
__device__ unsigned int g_negbits[BATCH * NTOT];   // fully rewritten each run
__device__ double       g_acc;                     // zero-init; reset by last select block
__device__ int          g_numpos[NGROUPS];         // reset by each select block after read
__device__ int          g_done;                    // reset by last select block
__device__ int          g_mdone;                   // reset by last select block

__device__ __forceinline__ float smooth_l1(float x) {
    float ax = fabsf(x);
    return ax < 1.0f ? (0.5f * x) * x : ax - 0.5f;
}

// fast softplus(-|x|) = log(1 + exp(-|x|)); e in (0,1] so 1+e has no cancellation
__device__ __forceinline__ float softplus_nabs(float ax) {
    return __logf(1.0f + __expf(-ax));
}

// One thread handles the 3 anchors (a=0..2) at one grid position (h,w).
// Per-block: precompute clamped wy per (row, gt, anchor) + per-row GT bitmask.
template<int H, int W, int STRIDE, int OFF, int SCALE>
__device__ __forceinline__ void match_body(int bx, int b,
                                           const float* __restrict__ pred,
                                           const float* __restrict__ gtb,
                                           const int*   __restrict__ gtl)
{
    constexpr int HW   = H * W;
    constexpr int ROWS = 256 / W;           // rows covered by one block (2/4/8)
    const int tid = threadIdx.x;

    __shared__ float4   sgt[NGT];
    __shared__ float    sarea[NGT];
    __shared__ int      slab[NGT];
    __shared__ float    swy[ROWS][NGT][3];  // clamped y-overlap per anchor
    __shared__ unsigned smask[ROWS];        // GTs with nonzero y-overlap (largest anchor)
    __shared__ float    swarp[8];
    __shared__ int      swpos[8];

    const float fs = (float)STRIDE;
    const float hh[3]    = {1.5f * fs, 2.0f * fs, 2.5f * fs};       // exact fp32
    const float areaA[3] = {9.0f * fs * fs, 16.0f * fs * fs, 25.0f * fs * fs};

    if (tid < NGT) {
        float4 g = ((const float4*)gtb)[b * NGT + tid];
        sgt[tid]   = g;
        sarea[tid] = (g.z - g.x) * (g.w - g.y);
        slab[tid]  = gtl[b * NGT + tid];
    }
    if (tid < ROWS) smask[tid] = 0u;
    __syncthreads();

    // build wy table + row masks: ROWS*NGT <= 256 items, one per thread
    if (tid < ROWS * NGT) {
        const int r = tid / NGT, j = tid % NGT;
        const int hR = bx * ROWS + r;
        const float cyr = (hR + 0.5f) * fs;                         // exact fp32
        float4 g = sgt[j];
        bool any = false;
        #pragma unroll
        for (int a = 0; a < 3; a++) {
            float wy = fminf(cyr + hh[a], g.w) - fmaxf(cyr - hh[a], g.y);
            wy = fmaxf(wy, 0.f);
            swy[r][j][a] = wy;
            any |= (wy > 0.f);
        }
        if (any) atomicOr(&smask[r], 1u << j);
    }
    __syncthreads();

    const int pl = bx * 256 + tid;           // HW multiple of 256
    const int w  = pl % W;
    const int r  = tid / W;                  // local row (warp-uniform: W >= 32)
    const float cx = (w + 0.5f) * fs;        // exact fp32

    const float x1a0 = cx - hh[0], x2a0 = cx + hh[0];
    const float x1a1 = cx - hh[1], x2a1 = cx + hh[1];
    const float x1a2 = cx - hh[2], x2a2 = cx + hh[2];

    // best per anchor: inter, denom (incl +1e-9), gt index
    float bI[3] = {0.f, 0.f, 0.f};
    float bD[3] = {1.f, 1.f, 1.f};
    int   bJ[3] = {0, 0, 0};

    unsigned m = smask[r];
    while (m) {
        const int j = __ffs(m) - 1;
        m &= m - 1;
        float4 g = sgt[j];
        // x-cull with the largest anchor (smaller anchors nested at same center)
        float wx2 = fminf(x2a2, g.z) - fmaxf(x1a2, g.x);
        if (wx2 > 0.f) {
            const float ab = sarea[j];
            const float x1s[3] = {x1a0, x1a1, x1a2};
            const float x2s[3] = {x2a0, x2a1, x2a2};
            #pragma unroll
            for (int a = 0; a < 3; a++) {
                float wx = fminf(x2s[a], g.z) - fmaxf(x1s[a], g.x);
                float inter = fmaxf(wx, 0.f) * swy[r][j][a];
                // same evaluation order as reference: ((aA + aB) - inter) + 1e-9
                float d = ((areaA[a] + ab) - inter) + 1e-9f;
                if (inter * bD[a] > bI[a] * d) { bI[a] = inter; bD[a] = d; bJ[a] = j; }
            }
        }
    }

    float lsum = 0.f;
    int   pcount = 0;
    const float* pb = pred + (size_t)b * 24 * HW + pl;

    #pragma unroll
    for (int a = 0; a < 3; a++) {
        // division-free thresholds: iou>=0.5 <=> 2*inter>=denom ; iou<0.4 <=> inter<0.4*denom
        bool pos = (bI[a] + bI[a] >= bD[a]);
        bool neg = (bI[a] < 0.4f * bD[a]);

        float x  = pb[(a * 8 + 4) * HW];
        float sp = softplus_nabs(fabsf(x));
        float Lneg = fmaxf(x, 0.f) + sp;    // BCE with target 0 (ranking value)
        g_negbits[b * NTOT + OFF + a * HW + pl] = neg ? __float_as_uint(Lneg) : 0u;

        if (pos) {
            pcount++;
            lsum += fmaxf(x, 0.f) - x + sp; // BCE with target 1

            float4 mb = sgt[bJ[a]];
            float sa = (3.0f + a) * fs;     // aw == ah == anchor size (exact)
            float gx = (mb.x + mb.z) * 0.5f;
            float gy = (mb.y + mb.w) * 0.5f;
            float gw = fmaxf(mb.z - mb.x, 1e-6f);
            float gh = fmaxf(mb.w - mb.y, 1e-6f);
            const int hR = bx * ROWS + r;
            float cy = (hR + 0.5f) * fs;
            float ttx = (gx - cx) / sa;
            float tty = (gy - cy) / sa;
            float ttw = logf(gw / sa);
            float tth = logf(gh / sa);

            float p0 = pb[(a * 8 + 0) * HW];
            float p1 = pb[(a * 8 + 1) * HW];
            float p2 = pb[(a * 8 + 2) * HW];
            float p3 = pb[(a * 8 + 3) * HW];
            lsum += smooth_l1(p0 - ttx) + smooth_l1(p1 - tty)
                  + smooth_l1(p2 - ttw) + smooth_l1(p3 - tth);

            float q0 = pb[(a * 8 + 5) * HW];
            float q1 = pb[(a * 8 + 6) * HW];
            float q2 = pb[(a * 8 + 7) * HW];
            float mm = fmaxf(q0, fmaxf(q1, q2));
            float lse = mm + logf(expf(q0 - mm) + expf(q1 - mm) + expf(q2 - mm));
            int lab = max(slab[bJ[a]], 0);
            float psel = (lab == 0) ? q0 : ((lab == 1) ? q1 : q2);
            lsum += lse - psel;
        }
    }

    // block reduce (256 threads = 8 warps)
    int lane = tid & 31, wid = tid >> 5;
    #pragma unroll
    for (int o = 16; o; o >>= 1) {
        lsum   += __shfl_down_sync(~0u, lsum, o);
        pcount += __shfl_down_sync(~0u, pcount, o);
    }
    if (lane == 0) { swarp[wid] = lsum; swpos[wid] = pcount; }
    __syncthreads();
    if (wid == 0) {
        lsum   = (lane < 8) ? swarp[lane] : 0.f;
        pcount = (lane < 8) ? swpos[lane] : 0;
        #pragma unroll
        for (int o = 4; o; o >>= 1) {
            lsum   += __shfl_down_sync(~0u, lsum, o);
            pcount += __shfl_down_sync(~0u, pcount, o);
        }
        if (lane == 0) {
            if (lsum != 0.f) atomicAdd(&g_acc, (double)lsum);
            if (pcount)      atomicAdd(&g_numpos[SCALE * BATCH + b], pcount);
            // publish this block's negbits/numpos, then bump the match counter
            __threadfence();
            atomicAdd(&g_mdone, 1);
        }
    }
}

// Hard-negative top-K sum per (image, scale) via 2-level radix select on
// positive-float bit patterns; runs in the tail blocks of the fused kernel.
__device__ __forceinline__ void select_body(int g, float* __restrict__ out)
{
    const int scale = g / BATCH;
    const int b     = g % BATCH;
    const int Ns[3]   = {49152, 12288, 3072};
    const int Offs[3] = {0, 49152, 61440};
    const int N   = Ns[scale];
    const int off = Offs[scale];
    const unsigned* base = g_negbits + b * NTOT + off;

    __shared__ int      hist[4096];
    __shared__ int      swsum[8];
    __shared__ unsigned s_T;
    __shared__ int      s_need, s_b1, s_cA, s_K;
    __shared__ float    s_v2;
    __shared__ float    sred[8];

    const int tid  = threadIdx.x;
    const int lane = tid & 31;
    const int wid  = tid >> 5;

    // ---- gate: wait for all match blocks ----
    if (tid == 0) {
        while (*(volatile int*)&g_mdone < MBLOCKS) __nanosleep(200);
        __threadfence();
        int np = g_numpos[g];
        g_numpos[g] = 0;                       // self-reset for next run
        s_K = 3 * max(1, np);
    }
    __syncthreads();
    const int K = s_K;

    // ---------- level 1: 2048 bins over bits[31:20] ----------
    for (int i = tid; i < 2048; i += NT) hist[i] = 0;
    __syncthreads();
    #pragma unroll 4
    for (int i = tid; i < N; i += NT) {
        unsigned u = base[i];
        if (u) {
            int bin = u >> 20;
            unsigned peers = __match_any_sync(__activemask(), bin);
            if ((int)(__ffs(peers) - 1) == lane)
                atomicAdd(&hist[bin], __popc(peers));
        }
    }
    __syncthreads();

    // suffix scan (descending bins), 8 bins/thread: thread t covers 2047-8t .. 2040-8t
    {
        int c[8], tot = 0;
        #pragma unroll
        for (int q = 0; q < 8; q++) { c[q] = hist[2047 - 8 * tid - q]; tot += c[q]; }
        int sc = tot;
        #pragma unroll
        for (int o = 1; o < 32; o <<= 1) {
            int v = __shfl_up_sync(~0u, sc, o);
            if (lane >= o) sc += v;
        }
        if (lane == 31) swsum[wid] = sc;
        __syncthreads();
        if (wid == 0) {
            int v = (lane < 8) ? swsum[lane] : 0;
            int s = v;
            #pragma unroll
            for (int o = 1; o < 8; o <<= 1) {
                int x = __shfl_up_sync(~0u, s, o);
                if (lane >= o) s += x;
            }
            if (lane < 8) swsum[lane] = s - v;   // exclusive warp offsets
            if (lane == 0) s_b1 = -1;            // sentinel
        }
        __syncthreads();
        int before = sc - tot + swsum[wid];      // count in all higher bins
        if (tid == NT - 1) hist[2048] = before + tot;   // grand total (scratch slot)
        __syncthreads();
        int grand = hist[2048];
        if (grand < K) {
            if (tid == 0) { s_T = 1u; s_need = 0; s_v2 = 0.f; }  // take all negs
        } else if (before < K && before + tot >= K) {            // unique owner thread
            int acc = before, bsel = 2047 - 8 * tid, cA = before;
            #pragma unroll
            for (int q = 0; q < 8; q++) {
                if (acc + c[q] >= K) { bsel = 2047 - 8 * tid - q; cA = acc; break; }
                acc += c[q];
            }
            s_b1 = bsel; s_cA = cA;
        }
        __syncthreads();
    }
    const int b1 = s_b1;

    if (b1 >= 0) {
        // ---------- level 2: 4096 bins over bits[19:8] within bin b1 ----------
        for (int i = tid; i < 4096; i += NT) hist[i] = 0;
        __syncthreads();
        #pragma unroll 4
        for (int i = tid; i < N; i += NT) {
            unsigned u = base[i];
            if (u && (int)(u >> 20) == b1) {
                int bin = (u >> 8) & 0xFFF;
                unsigned peers = __match_any_sync(__activemask(), bin);
                if ((int)(__ffs(peers) - 1) == lane)
                    atomicAdd(&hist[bin], __popc(peers));
            }
        }
        __syncthreads();

        // suffix scan, 16 bins/thread: thread t covers 4095-16t .. 4080-16t
        {
            const int K2 = K - s_cA;      // >= 1, crossing guaranteed inside b1
            int c[16], tot = 0;
            #pragma unroll
            for (int q = 0; q < 16; q++) { c[q] = hist[4095 - 16 * tid - q]; tot += c[q]; }
            int sc = tot;
            #pragma unroll
            for (int o = 1; o < 32; o <<= 1) {
                int v = __shfl_up_sync(~0u, sc, o);
                if (lane >= o) sc += v;
            }
            if (lane == 31) swsum[wid] = sc;
            __syncthreads();
            if (wid == 0) {
                int v = (lane < 8) ? swsum[lane] : 0;
                int s = v;
                #pragma unroll
                for (int o = 1; o < 8; o <<= 1) {
                    int x = __shfl_up_sync(~0u, s, o);
                    if (lane >= o) s += x;
                }
                if (lane < 8) swsum[lane] = s - v;
            }
            __syncthreads();
            int before = sc - tot + swsum[wid];
            if (before < K2 && before + tot >= K2) {    // unique owner
                int acc = before, b2 = 4095 - 16 * tid, cSA = before;
                #pragma unroll
                for (int q = 0; q < 16; q++) {
                    if (acc + c[q] >= K2) { b2 = 4095 - 16 * tid - q; cSA = acc; break; }
                    acc += c[q];
                }
                s_need = K2 - cSA;
                s_T = ((unsigned)b1 << 20) + (((unsigned)b2 + 1u) << 8); // strictly above sub-bin
                // boundary values share 24 leading bits -> midpoint error < 2^-16 rel
                s_v2 = __uint_as_float(((unsigned)b1 << 20) | ((unsigned)b2 << 8) | 0x80u);
            }
            __syncthreads();
        }
    }

    // ---------- sum values strictly above threshold, plus `need` boundary values ----------
    const unsigned T = s_T;
    float sum = 0.f;
    #pragma unroll 4
    for (int i = tid; i < N; i += NT) {
        unsigned u = base[i];
        if (u >= T) sum += __uint_as_float(u);
    }
    #pragma unroll
    for (int o = 16; o; o >>= 1) sum += __shfl_down_sync(~0u, sum, o);
    if (lane == 0) sred[wid] = sum;
    __syncthreads();
    if (wid == 0) {
        sum = (lane < 8) ? sred[lane] : 0.f;
        #pragma unroll
        for (int o = 4; o; o >>= 1) sum += __shfl_down_sync(~0u, sum, o);
        if (lane == 0) {
            atomicAdd(&g_acc, (double)(sum + (float)s_need * s_v2));
            __threadfence();
            int done = atomicAdd(&g_done, 1);
            if (done == NGROUPS - 1) {              // last select block: finalize + reset
                __threadfence();
                double total = atomicAdd(&g_acc, 0.0);
                out[0] = (float)(total * (1.0 / 64.0));
                g_acc   = 0.0;
                g_done  = 0;
                g_mdone = 0;
            }
        }
    }
}

// Single fused launch: blocks [0,MBLOCKS) do match tiles (3 scales interleaved
// per image); tail NGROUPS blocks run hard-negative select after a spin-gate.
// Select blocks have the highest block indices -> scheduled last; match blocks
// never wait on them, so the gate cannot deadlock.
__global__ void __launch_bounds__(NT) fused_kernel(const float* __restrict__ p0,
                                                   const float* __restrict__ p1,
                                                   const float* __restrict__ p2,
                                                   const float* __restrict__ gtb,
                                                   const int*   __restrict__ gtl,
                                                   float* __restrict__ out)
{
    const int bid = blockIdx.x;
    if (bid < MBLOCKS) {
        const int bx = bid % 84, b = bid / 84;
        if (bx < 64)      match_body<128, 128,  8,     0, 0>(bx,      b, p0, gtb, gtl);
        else if (bx < 80) match_body< 64,  64, 16, 49152, 1>(bx - 64, b, p1, gtb, gtl);
        else              match_body< 32,  32, 32, 61440, 2>(bx - 80, b, p2, gtb, gtl);
    } else {
        select_body(bid - MBLOCKS, out);
    }
}

extern "C" void kernel_launch(void* const* d_in, const int* in_sizes, int n_in,
                              void* d_out, int out_size)
{
    // identify inputs by element count (robust to metadata ordering)
    const float *pred0 = nullptr, *pred1 = nullptr, *pred2 = nullptr, *gtb = nullptr;
    const int *gtl = nullptr;
    for (int i = 0; i < n_in; i++) {
        switch (in_sizes[i]) {
            case 25165824: pred0 = (const float*)d_in[i]; break;  // 64*24*128*128
            case 6291456:  pred1 = (const float*)d_in[i]; break;  // 64*24*64*64
            case 1572864:  pred2 = (const float*)d_in[i]; break;  // 64*24*32*32
            case 8192:     gtb   = (const float*)d_in[i]; break;  // 64*32*4
            case 2048:     gtl   = (const int*)d_in[i];   break;  // 64*32
            default: break;                                       // anchors: recomputed
        }
    }

    fused_kernel<<<MBLOCKS + NGROUPS, NT>>>(pred0, pred1, pred2, gtb, gtl, (float*)d_out);
}

// round 14
// speedup vs baseline: 2.2081x; 2.2081x over previous
#include <cuda_runtime.h>
#include <math.h>

#define BATCH   64
#define NGT     32
#define NTOT    64512
#define NGROUPS 192   // 3 scales * 64 images

// ---- scratch (no allocations allowed); all state self-resets each run ----
__device__ unsigned int g_negbits[BATCH * NTOT];   // fully rewritten each run
__device__ double       g_acc;                     // zero-init; reset by last select block
__device__ int          g_numpos[NGROUPS];         // reset by each select block after read
__device__ int          g_done;                    // reset by last select block

__device__ __forceinline__ float smooth_l1(float x) {
    float ax = fabsf(x);
    return ax < 1.0f ? (0.5f * x) * x : ax - 0.5f;
}

// fast softplus(-|x|) = log(1 + exp(-|x|)); e in (0,1] so 1+e has no cancellation
__device__ __forceinline__ float softplus_nabs(float ax) {
    return __logf(1.0f + __expf(-ax));
}

// One thread handles the 3 anchors (a=0..2) at one grid position (h,w).
// Per-block: precompute clamped wy per (row, gt, anchor) + per-row GT bitmask.
template<int H, int W, int STRIDE, int OFF, int SCALE>
__device__ __forceinline__ void match_body(int bx, int b,
                                           const float* __restrict__ pred,
                                           const float* __restrict__ gtb,
                                           const int*   __restrict__ gtl)
{
    constexpr int HW   = H * W;
    constexpr int ROWS = 256 / W;           // rows covered by one block (2/4/8)
    const int tid = threadIdx.x;

    __shared__ float4   sgt[NGT];
    __shared__ float    sarea[NGT];
    __shared__ int      slab[NGT];
    __shared__ float    swy[ROWS][NGT][3];  // clamped y-overlap per anchor
    __shared__ unsigned smask[ROWS];        // GTs with nonzero y-overlap (largest anchor)
    __shared__ float    swarp[8];
    __shared__ int      swpos[8];

    const float fs = (float)STRIDE;
    const float hh[3]    = {1.5f * fs, 2.0f * fs, 2.5f * fs};       // exact fp32
    const float areaA[3] = {9.0f * fs * fs, 16.0f * fs * fs, 25.0f * fs * fs};

    if (tid < NGT) {
        float4 g = ((const float4*)gtb)[b * NGT + tid];
        sgt[tid]   = g;
        sarea[tid] = (g.z - g.x) * (g.w - g.y);
        slab[tid]  = gtl[b * NGT + tid];
    }
    if (tid < ROWS) smask[tid] = 0u;
    __syncthreads();

    // build wy table + row masks: ROWS*NGT <= 256 items, one per thread
    if (tid < ROWS * NGT) {
        const int r = tid / NGT, j = tid % NGT;
        const int hR = bx * ROWS + r;
        const float cyr = (hR + 0.5f) * fs;                         // exact fp32
        float4 g = sgt[j];
        bool any = false;
        #pragma unroll
        for (int a = 0; a < 3; a++) {
            float wy = fminf(cyr + hh[a], g.w) - fmaxf(cyr - hh[a], g.y);
            wy = fmaxf(wy, 0.f);
            swy[r][j][a] = wy;
            any |= (wy > 0.f);
        }
        if (any) atomicOr(&smask[r], 1u << j);
    }
    __syncthreads();

    const int pl = bx * 256 + tid;           // HW multiple of 256
    const int w  = pl % W;
    const int r  = tid / W;                  // local row (warp-uniform: W >= 32)
    const float cx = (w + 0.5f) * fs;        // exact fp32

    const float x1a0 = cx - hh[0], x2a0 = cx + hh[0];
    const float x1a1 = cx - hh[1], x2a1 = cx + hh[1];
    const float x1a2 = cx - hh[2], x2a2 = cx + hh[2];

    // best per anchor: inter, denom (incl +1e-9), gt index
    float bI[3] = {0.f, 0.f, 0.f};
    float bD[3] = {1.f, 1.f, 1.f};
    int   bJ[3] = {0, 0, 0};

    unsigned m = smask[r];
    while (m) {
        const int j = __ffs(m) - 1;
        m &= m - 1;
        float4 g = sgt[j];
        // x-cull with the largest anchor (smaller anchors nested at same center)
        float wx2 = fminf(x2a2, g.z) - fmaxf(x1a2, g.x);
        if (wx2 > 0.f) {
            const float ab = sarea[j];
            const float x1s[3] = {x1a0, x1a1, x1a2};
            const float x2s[3] = {x2a0, x2a1, x2a2};
            #pragma unroll
            for (int a = 0; a < 3; a++) {
                float wx = fminf(x2s[a], g.z) - fmaxf(x1s[a], g.x);
                float inter = fmaxf(wx, 0.f) * swy[r][j][a];
                // same evaluation order as reference: ((aA + aB) - inter) + 1e-9
                float d = ((areaA[a] + ab) - inter) + 1e-9f;
                if (inter * bD[a] > bI[a] * d) { bI[a] = inter; bD[a] = d; bJ[a] = j; }
            }
        }
    }

    float lsum = 0.f;
    int   pcount = 0;
    const float* pb = pred + (size_t)b * 24 * HW + pl;

    #pragma unroll
    for (int a = 0; a < 3; a++) {
        // division-free thresholds: iou>=0.5 <=> 2*inter>=denom ; iou<0.4 <=> inter<0.4*denom
        bool pos = (bI[a] + bI[a] >= bD[a]);
        bool neg = (bI[a] < 0.4f * bD[a]);

        float x  = pb[(a * 8 + 4) * HW];
        float sp = softplus_nabs(fabsf(x));
        float Lneg = fmaxf(x, 0.f) + sp;    // BCE with target 0 (ranking value)
        g_negbits[b * NTOT + OFF + a * HW + pl] = neg ? __float_as_uint(Lneg) : 0u;

        if (pos) {
            pcount++;
            lsum += fmaxf(x, 0.f) - x + sp; // BCE with target 1

            float4 mb = sgt[bJ[a]];
            float sa = (3.0f + a) * fs;     // aw == ah == anchor size (exact)
            float gx = (mb.x + mb.z) * 0.5f;
            float gy = (mb.y + mb.w) * 0.5f;
            float gw = fmaxf(mb.z - mb.x, 1e-6f);
            float gh = fmaxf(mb.w - mb.y, 1e-6f);
            const int hR = bx * ROWS + r;
            float cy = (hR + 0.5f) * fs;
            float ttx = (gx - cx) / sa;
            float tty = (gy - cy) / sa;
            float ttw = logf(gw / sa);
            float tth = logf(gh / sa);

            float p0 = pb[(a * 8 + 0) * HW];
            float p1 = pb[(a * 8 + 1) * HW];
            float p2 = pb[(a * 8 + 2) * HW];
            float p3 = pb[(a * 8 + 3) * HW];
            lsum += smooth_l1(p0 - ttx) + smooth_l1(p1 - tty)
                  + smooth_l1(p2 - ttw) + smooth_l1(p3 - tth);

            float q0 = pb[(a * 8 + 5) * HW];
            float q1 = pb[(a * 8 + 6) * HW];
            float q2 = pb[(a * 8 + 7) * HW];
            float mm = fmaxf(q0, fmaxf(q1, q2));
            float lse = mm + logf(expf(q0 - mm) + expf(q1 - mm) + expf(q2 - mm));
            int lab = max(slab[bJ[a]], 0);
            float psel = (lab == 0) ? q0 : ((lab == 1) ? q1 : q2);
            lsum += lse - psel;
        }
    }

    // block reduce (256 threads = 8 warps)
    int lane = tid & 31, wid = tid >> 5;
    #pragma unroll
    for (int o = 16; o; o >>= 1) {
        lsum   += __shfl_down_sync(~0u, lsum, o);
        pcount += __shfl_down_sync(~0u, pcount, o);
    }
    if (lane == 0) { swarp[wid] = lsum; swpos[wid] = pcount; }
    __syncthreads();
    if (wid == 0) {
        lsum   = (lane < 8) ? swarp[lane] : 0.f;
        pcount = (lane < 8) ? swpos[lane] : 0;
        #pragma unroll
        for (int o = 4; o; o >>= 1) {
            lsum   += __shfl_down_sync(~0u, lsum, o);
            pcount += __shfl_down_sync(~0u, pcount, o);
        }
        if (lane == 0) {
            if (lsum != 0.f) atomicAdd(&g_acc, (double)lsum);
            if (pcount)      atomicAdd(&g_numpos[SCALE * BATCH + b], pcount);
        }
    }
}

// Fused: all three scales in one launch so scale-1/2 fill SMs alongside scale-0.
// blockIdx.x: [0,64) scale0, [64,80) scale1, [80,84) scale2.
__global__ void __launch_bounds__(256) match_all(const float* __restrict__ p0,
                                                 const float* __restrict__ p1,
                                                 const float* __restrict__ p2,
                                                 const float* __restrict__ gtb,
                                                 const int*   __restrict__ gtl)
{
    const int bx = blockIdx.x, b = blockIdx.y;
    if (bx < 64)      match_body<128, 128,  8,     0, 0>(bx,      b, p0, gtb, gtl);
    else if (bx < 80) match_body< 64,  64, 16, 49152, 1>(bx - 64, b, p1, gtb, gtl);
    else              match_body< 32,  32, 32, 61440, 2>(bx - 80, b, p2, gtb, gtl);
}

// Per (image, scale) hard-negative top-K sum via 2-level radix select on
// positive-float bit patterns. 1 block per group; data is L2/L1-resident.
// Histogram atomics are warp-aggregated; boundary search is a parallel
// block suffix-scan. The LAST block to finish emits the final output and
// resets all global state for the next (graph-replayed) run.
__global__ void __launch_bounds__(1024) select_kernel(float* __restrict__ out)
{
    const int g = blockIdx.x;             // 0..191
    const int scale = g / BATCH;
    const int b     = g % BATCH;
    const int Ns[3]   = {49152, 12288, 3072};
    const int Offs[3] = {0, 49152, 61440};
    const int N   = Ns[scale];
    const int off = Offs[scale];
    const unsigned* base = g_negbits + b * NTOT + off;

    __shared__ int      hist[4096];
    __shared__ int      swsum[32];
    __shared__ unsigned s_T;
    __shared__ int      s_need, s_b1, s_cA, s_K;
    __shared__ float    s_v2;
    __shared__ float    sred[32];

    const int tid  = threadIdx.x;
    const int lane = tid & 31;
    const int wid  = tid >> 5;
    const int NT   = 1024;

    if (tid == 0) {
        int np = g_numpos[g];
        g_numpos[g] = 0;                   // self-reset for next run
        s_K = 3 * max(1, np);
    }
    __syncthreads();
    const int K = s_K;

    // ---------- level 1: 2048 bins over bits[31:20] ----------
    for (int i = tid; i < 2048; i += NT) hist[i] = 0;
    __syncthreads();
    for (int i = tid; i < N; i += NT) {
        unsigned u = base[i];
        if (u) {
            int bin = u >> 20;
            unsigned peers = __match_any_sync(__activemask(), bin);
            if ((int)(__ffs(peers) - 1) == lane)
                atomicAdd(&hist[bin], __popc(peers));
        }
    }
    __syncthreads();

    // suffix scan (descending bins), 2 bins/thread: thread t covers 2047-2t, 2046-2t
    {
        int c0 = hist[2047 - 2 * tid];
        int c1 = hist[2046 - 2 * tid];
        int tot = c0 + c1;
        // inclusive warp scan in t-order (== descending bin order)
        int sc = tot;
        #pragma unroll
        for (int o = 1; o < 32; o <<= 1) {
            int v = __shfl_up_sync(~0u, sc, o);
            if (lane >= o) sc += v;
        }
        if (lane == 31) swsum[wid] = sc;
        __syncthreads();
        if (wid == 0) {
            int v = (lane < 32) ? swsum[lane] : 0;
            int s = v;
            #pragma unroll
            for (int o = 1; o < 32; o <<= 1) {
                int x = __shfl_up_sync(~0u, s, o);
                if (lane >= o) s += x;
            }
            swsum[lane] = s - v;          // exclusive warp offsets
            if (lane == 31) s_b1 = -1;    // sentinel
        }
        __syncthreads();
        int before = sc - tot + swsum[wid];     // count in all higher bins
        if (tid == NT - 1) hist[2048] = before + tot;   // grand total (scratch slot)
        __syncthreads();
        int grand = hist[2048];
        if (grand < K) {
            if (tid == 0) { s_T = 1u; s_need = 0; s_v2 = 0.f; }  // take all negs
        } else if (before < K && before + tot >= K) {            // unique owner thread
            if (before + c0 >= K) { s_b1 = 2047 - 2 * tid; s_cA = before; }
            else                  { s_b1 = 2046 - 2 * tid; s_cA = before + c0; }
        }
        __syncthreads();
    }
    const int b1 = s_b1;

    if (b1 >= 0) {
        // ---------- level 2: 4096 bins over bits[19:8] within bin b1 ----------
        for (int i = tid; i < 4096; i += NT) hist[i] = 0;
        __syncthreads();
        for (int i = tid; i < N; i += NT) {
            unsigned u = base[i];
            if (u && (int)(u >> 20) == b1) {
                int bin = (u >> 8) & 0xFFF;
                unsigned peers = __match_any_sync(__activemask(), bin);
                if ((int)(__ffs(peers) - 1) == lane)
                    atomicAdd(&hist[bin], __popc(peers));
            }
        }
        __syncthreads();

        // suffix scan, 4 bins/thread: thread t covers 4095-4t .. 4092-4t
        {
            const int K2 = K - s_cA;      // >= 1, crossing guaranteed inside b1
            int c[4], tot = 0;
            #pragma unroll
            for (int q = 0; q < 4; q++) { c[q] = hist[4095 - 4 * tid - q]; tot += c[q]; }
            int sc = tot;
            #pragma unroll
            for (int o = 1; o < 32; o <<= 1) {
                int v = __shfl_up_sync(~0u, sc, o);
                if (lane >= o) sc += v;
            }
            if (lane == 31) swsum[wid] = sc;
            __syncthreads();
            if (wid == 0) {
                int v = (lane < 32) ? swsum[lane] : 0;
                int s = v;
                #pragma unroll
                for (int o = 1; o < 32; o <<= 1) {
                    int x = __shfl_up_sync(~0u, s, o);
                    if (lane >= o) s += x;
                }
                swsum[lane] = s - v;
            }
            __syncthreads();
            int before = sc - tot + swsum[wid];
            if (before < K2 && before + tot >= K2) {    // unique owner
                int acc = before, b2 = 4095 - 4 * tid, cSA = before;
                #pragma unroll
                for (int q = 0; q < 4; q++) {
                    if (acc + c[q] >= K2) { b2 = 4095 - 4 * tid - q; cSA = acc; break; }
                    acc += c[q];
                }
                s_need = K2 - cSA;
                s_T = ((unsigned)b1 << 20) + (((unsigned)b2 + 1u) << 8); // strictly above sub-bin
                // boundary values share 24 leading bits -> midpoint error < 2^-16 rel
                s_v2 = __uint_as_float(((unsigned)b1 << 20) | ((unsigned)b2 << 8) | 0x80u);
            }
            __syncthreads();
        }
    }

    // ---------- sum values strictly above threshold, plus `need` boundary values ----------
    const unsigned T = s_T;
    float sum = 0.f;
    for (int i = tid; i < N; i += NT) {
        unsigned u = base[i];
        if (u >= T) sum += __uint_as_float(u);
    }
    #pragma unroll
    for (int o = 16; o; o >>= 1) sum += __shfl_down_sync(~0u, sum, o);
    if (lane == 0) sred[wid] = sum;
    __syncthreads();
    if (wid == 0) {
        sum = (lane < 32) ? sred[lane] : 0.f;
        #pragma unroll
        for (int o = 16; o; o >>= 1) sum += __shfl_down_sync(~0u, sum, o);
        if (lane == 0) {
            atomicAdd(&g_acc, (double)(sum + (float)s_need * s_v2));
            // folded finalization: last block to complete writes output + resets state
            __threadfence();
            int done = atomicAdd(&g_done, 1);
            if (done == NGROUPS - 1) {
                __threadfence();
                double total = atomicAdd(&g_acc, 0.0);   // coherent read after fence
                out[0] = (float)(total * (1.0 / 64.0));
                g_acc  = 0.0;
                g_done = 0;
            }
        }
    }
}

extern "C" void kernel_launch(void* const* d_in, const int* in_sizes, int n_in,
                              void* d_out, int out_size)
{
    // identify inputs by element count (robust to metadata ordering)
    const float *pred0 = nullptr, *pred1 = nullptr, *pred2 = nullptr, *gtb = nullptr;
    const int *gtl = nullptr;
    for (int i = 0; i < n_in; i++) {
        switch (in_sizes[i]) {
            case 25165824: pred0 = (const float*)d_in[i]; break;  // 64*24*128*128
            case 6291456:  pred1 = (const float*)d_in[i]; break;  // 64*24*64*64
            case 1572864:  pred2 = (const float*)d_in[i]; break;  // 64*24*32*32
            case 8192:     gtb   = (const float*)d_in[i]; break;  // 64*32*4
            case 2048:     gtl   = (const int*)d_in[i];   break;  // 64*32
            default: break;                                       // anchors: recomputed
        }
    }

    match_all<<<dim3(84, BATCH), 256>>>(pred0, pred1, pred2, gtb, gtl);
    select_kernel<<<NGROUPS, 1024>>>((float*)d_out);
}

// round 16
// speedup vs baseline: 2.3055x; 1.0441x over previous
#include <cuda_runtime.h>
#include <math.h>

#define BATCH   64
#define NGT     32
#define NTOT    64512
#define NGROUPS 192   // 3 scales * 64 images

// ---- scratch (no allocations allowed); all state self-resets each run ----
__device__ unsigned int g_negbits[BATCH * NTOT];   // fully rewritten each run
__device__ double       g_acc;                     // zero-init; reset by last select block
__device__ int          g_numpos[NGROUPS];         // reset by each select block after read
__device__ int          g_done;                    // reset by last select block

__device__ __forceinline__ float smooth_l1(float x) {
    float ax = fabsf(x);
    return ax < 1.0f ? (0.5f * x) * x : ax - 0.5f;
}

// fast softplus(-|x|) = log(1 + exp(-|x|)); e in (0,1] so 1+e has no cancellation
__device__ __forceinline__ float softplus_nabs(float ax) {
    return __logf(1.0f + __expf(-ax));
}

// One thread handles the 3 anchors (a=0..2) at one grid position (h,w).
// Per-block: precompute clamped wy per (row, gt, anchor) + per-row GT bitmask.
template<int H, int W, int STRIDE, int OFF, int SCALE>
__device__ __forceinline__ void match_body(int bx, int b,
                                           const float* __restrict__ pred,
                                           const float* __restrict__ gtb,
                                           const int*   __restrict__ gtl)
{
    constexpr int HW   = H * W;
    constexpr int ROWS = 256 / W;           // rows covered by one block (2/4/8)
    const int tid = threadIdx.x;

    __shared__ float4   sgt[NGT];
    __shared__ float    sarea[NGT];
    __shared__ int      slab[NGT];
    __shared__ float    swy[ROWS][NGT][3];  // clamped y-overlap per anchor
    __shared__ unsigned smask[ROWS];        // GTs with nonzero y-overlap (largest anchor)
    __shared__ float    swarp[8];
    __shared__ int      swpos[8];

    const float fs = (float)STRIDE;
    const float hh[3]    = {1.5f * fs, 2.0f * fs, 2.5f * fs};       // exact fp32
    const float areaA[3] = {9.0f * fs * fs, 16.0f * fs * fs, 25.0f * fs * fs};

    if (tid < NGT) {
        float4 g = ((const float4*)gtb)[b * NGT + tid];
        sgt[tid]   = g;
        sarea[tid] = (g.z - g.x) * (g.w - g.y);
        slab[tid]  = gtl[b * NGT + tid];
    }
    if (tid < ROWS) smask[tid] = 0u;
    __syncthreads();

    // build wy table + row masks: ROWS*NGT <= 256 items, one per thread
    if (tid < ROWS * NGT) {
        const int r = tid / NGT, j = tid % NGT;
        const int hR = bx * ROWS + r;
        const float cyr = (hR + 0.5f) * fs;                         // exact fp32
        float4 g = sgt[j];
        bool any = false;
        #pragma unroll
        for (int a = 0; a < 3; a++) {
            float wy = fminf(cyr + hh[a], g.w) - fmaxf(cyr - hh[a], g.y);
            wy = fmaxf(wy, 0.f);
            swy[r][j][a] = wy;
            any |= (wy > 0.f);
        }
        if (any) atomicOr(&smask[r], 1u << j);
    }
    __syncthreads();

    const int pl = bx * 256 + tid;           // HW multiple of 256
    const int w  = pl % W;
    const int r  = tid / W;                  // local row (warp-uniform: W >= 32)
    const float cx = (w + 0.5f) * fs;        // exact fp32

    const float x1a0 = cx - hh[0], x2a0 = cx + hh[0];
    const float x1a1 = cx - hh[1], x2a1 = cx + hh[1];
    const float x1a2 = cx - hh[2], x2a2 = cx + hh[2];

    // best per anchor: inter, denom (incl +1e-9), gt index
    float bI[3] = {0.f, 0.f, 0.f};
    float bD[3] = {1.f, 1.f, 1.f};
    int   bJ[3] = {0, 0, 0};

    unsigned m = smask[r];
    while (m) {
        const int j = __ffs(m) - 1;
        m &= m - 1;
        float4 g = sgt[j];
        // x-cull with the largest anchor (smaller anchors nested at same center)
        float wx2 = fminf(x2a2, g.z) - fmaxf(x1a2, g.x);
        if (wx2 > 0.f) {
            const float ab = sarea[j];
            const float x1s[3] = {x1a0, x1a1, x1a2};
            const float x2s[3] = {x2a0, x2a1, x2a2};
            #pragma unroll
            for (int a = 0; a < 3; a++) {
                float wx = fminf(x2s[a], g.z) - fmaxf(x1s[a], g.x);
                float inter = fmaxf(wx, 0.f) * swy[r][j][a];
                // same evaluation order as reference: ((aA + aB) - inter) + 1e-9
                float d = ((areaA[a] + ab) - inter) + 1e-9f;
                if (inter * bD[a] > bI[a] * d) { bI[a] = inter; bD[a] = d; bJ[a] = j; }
            }
        }
    }

    float lsum = 0.f;
    int   pcount = 0;
    const float* pb = pred + (size_t)b * 24 * HW + pl;

    #pragma unroll
    for (int a = 0; a < 3; a++) {
        // division-free thresholds: iou>=0.5 <=> 2*inter>=denom ; iou<0.4 <=> inter<0.4*denom
        bool pos = (bI[a] + bI[a] >= bD[a]);
        bool neg = (bI[a] < 0.4f * bD[a]);

        float x  = pb[(a * 8 + 4) * HW];
        float sp = softplus_nabs(fabsf(x));
        float Lneg = fmaxf(x, 0.f) + sp;    // BCE with target 0 (ranking value)
        g_negbits[b * NTOT + OFF + a * HW + pl] = neg ? __float_as_uint(Lneg) : 0u;

        if (pos) {
            pcount++;
            lsum += fmaxf(x, 0.f) - x + sp; // BCE with target 1

            float4 mb = sgt[bJ[a]];
            float sa = (3.0f + a) * fs;     // aw == ah == anchor size (exact)
            float gx = (mb.x + mb.z) * 0.5f;
            float gy = (mb.y + mb.w) * 0.5f;
            float gw = fmaxf(mb.z - mb.x, 1e-6f);
            float gh = fmaxf(mb.w - mb.y, 1e-6f);
            const int hR = bx * ROWS + r;
            float cy = (hR + 0.5f) * fs;
            float ttx = (gx - cx) / sa;
            float tty = (gy - cy) / sa;
            float ttw = logf(gw / sa);
            float tth = logf(gh / sa);

            float p0 = pb[(a * 8 + 0) * HW];
            float p1 = pb[(a * 8 + 1) * HW];
            float p2 = pb[(a * 8 + 2) * HW];
            float p3 = pb[(a * 8 + 3) * HW];
            lsum += smooth_l1(p0 - ttx) + smooth_l1(p1 - tty)
                  + smooth_l1(p2 - ttw) + smooth_l1(p3 - tth);

            float q0 = pb[(a * 8 + 5) * HW];
            float q1 = pb[(a * 8 + 6) * HW];
            float q2 = pb[(a * 8 + 7) * HW];
            float mm = fmaxf(q0, fmaxf(q1, q2));
            float lse = mm + logf(expf(q0 - mm) + expf(q1 - mm) + expf(q2 - mm));
            int lab = max(slab[bJ[a]], 0);
            float psel = (lab == 0) ? q0 : ((lab == 1) ? q1 : q2);
            lsum += lse - psel;
        }
    }

    // block reduce (256 threads = 8 warps)
    int lane = tid & 31, wid = tid >> 5;
    #pragma unroll
    for (int o = 16; o; o >>= 1) {
        lsum   += __shfl_down_sync(~0u, lsum, o);
        pcount += __shfl_down_sync(~0u, pcount, o);
    }
    if (lane == 0) { swarp[wid] = lsum; swpos[wid] = pcount; }
    __syncthreads();
    if (wid == 0) {
        lsum   = (lane < 8) ? swarp[lane] : 0.f;
        pcount = (lane < 8) ? swpos[lane] : 0;
        #pragma unroll
        for (int o = 4; o; o >>= 1) {
            lsum   += __shfl_down_sync(~0u, lsum, o);
            pcount += __shfl_down_sync(~0u, pcount, o);
        }
        if (lane == 0) {
            if (lsum != 0.f) atomicAdd(&g_acc, (double)lsum);
            if (pcount)      atomicAdd(&g_numpos[SCALE * BATCH + b], pcount);
        }
    }
}

// Fused: all three scales in one launch so scale-1/2 fill SMs alongside scale-0.
__global__ void __launch_bounds__(256) match_all(const float* __restrict__ p0,
                                                 const float* __restrict__ p1,
                                                 const float* __restrict__ p2,
                                                 const float* __restrict__ gtb,
                                                 const int*   __restrict__ gtl)
{
    const int bx = blockIdx.x, b = blockIdx.y;
    if (bx < 64)      match_body<128, 128,  8,     0, 0>(bx,      b, p0, gtb, gtl);
    else if (bx < 80) match_body< 64,  64, 16, 49152, 1>(bx - 64, b, p1, gtb, gtl);
    else              match_body< 32,  32, 32, 61440, 2>(bx - 80, b, p2, gtb, gtl);
}

// Per (image, scale) hard-negative top-K sum. TWO vectorized passes:
//  A: grand sum + 2048-bin count hist  -> b1 (or take-all shortcut)
//  B: exact sum above bin b1 + 4096-bin level-2 count hist of b1 members
//     -> selected-in-b1 portion reconstructed from counts x sub-bin midpoints.
__global__ void __launch_bounds__(1024) select_kernel(float* __restrict__ out)
{
    const int g = blockIdx.x;             // 0..191
    const int scale = g / BATCH;
    const int b     = g % BATCH;
    const int Ns[3]   = {49152, 12288, 3072};
    const int Offs[3] = {0, 49152, 61440};
    const int N   = Ns[scale];
    const int off = Offs[scale];
    const unsigned* __restrict__ base = g_negbits + b * NTOT + off;

    __shared__ int      hist[4096];
    __shared__ int      swsum[32];
    __shared__ float    sred[32];
    __shared__ int      s_b1, s_cA, s_K, s_b2, s_need;
    __shared__ float    s_ans, s_gsum, s_asum;

    const int tid  = threadIdx.x;
    const int lane = tid & 31;
    const int wid  = tid >> 5;
    const int NT   = 1024;

    if (tid == 0) {
        int np = g_numpos[g];
        g_numpos[g] = 0;                   // self-reset for next run
        s_K = 3 * max(1, np);
    }
    __syncthreads();
    const int K = s_K;

    // ---------- pass A: grand sum + 2048-bin count hist (uint4 loads) ----------
    for (int i = tid; i < 2048; i += NT) hist[i] = 0;
    __syncthreads();
    float gsum = 0.f;
    for (int i = 4 * tid; i < N; i += 4 * NT) {
        uint4 v = *(const uint4*)(base + i);
        unsigned uu[4] = {v.x, v.y, v.z, v.w};
        #pragma unroll
        for (int q = 0; q < 4; q++) {
            unsigned u = uu[q];
            if (u) {
                gsum += __uint_as_float(u);
                int bin = u >> 20;
                unsigned peers = __match_any_sync(__activemask(), bin);
                if ((int)(__ffs(peers) - 1) == lane)
                    atomicAdd(&hist[bin], __popc(peers));
            }
        }
    }
    // block-reduce grand sum
    #pragma unroll
    for (int o = 16; o; o >>= 1) gsum += __shfl_down_sync(~0u, gsum, o);
    if (lane == 0) sred[wid] = gsum;
    __syncthreads();
    if (wid == 0) {
        float v = (lane < 32) ? sred[lane] : 0.f;
        #pragma unroll
        for (int o = 16; o; o >>= 1) v += __shfl_down_sync(~0u, v, o);
        if (lane == 0) s_gsum = v;
    }
    __syncthreads();

    // suffix scan (descending bins), 2 bins/thread: thread t covers 2047-2t, 2046-2t
    {
        int c0 = hist[2047 - 2 * tid];
        int c1 = hist[2046 - 2 * tid];
        int tot = c0 + c1;
        int sc = tot;
        #pragma unroll
        for (int o = 1; o < 32; o <<= 1) {
            int v = __shfl_up_sync(~0u, sc, o);
            if (lane >= o) sc += v;
        }
        if (lane == 31) swsum[wid] = sc;
        __syncthreads();
        if (wid == 0) {
            int v = (lane < 32) ? swsum[lane] : 0;
            int s = v;
            #pragma unroll
            for (int o = 1; o < 32; o <<= 1) {
                int x = __shfl_up_sync(~0u, s, o);
                if (lane >= o) s += x;
            }
            swsum[lane] = s - v;          // exclusive warp offsets
            if (lane == 31) s_b1 = -1;    // sentinel
        }
        __syncthreads();
        int before = sc - tot + swsum[wid];     // count in all higher bins
        if (tid == NT - 1) hist[2048] = before + tot;   // grand count (scratch slot)
        __syncthreads();
        int grand = hist[2048];
        if (grand <= K) {
            if (tid == 0) s_ans = s_gsum;                // take ALL negatives
        } else if (before < K && before + tot >= K) {    // unique owner thread
            if (before + c0 >= K) { s_b1 = 2047 - 2 * tid; s_cA = before; }
            else                  { s_b1 = 2046 - 2 * tid; s_cA = before + c0; }
        }
        __syncthreads();
    }
    const int b1 = s_b1;

    if (b1 >= 0) {
        // ------ pass B: exact sum above bin b1 + level-2 hist of b1 members ------
        for (int i = tid; i < 4096; i += NT) hist[i] = 0;
        __syncthreads();
        const unsigned hiT = (unsigned)(b1 + 1) << 20;
        float asum = 0.f;
        for (int i = 4 * tid; i < N; i += 4 * NT) {
            uint4 v = *(const uint4*)(base + i);
            unsigned uu[4] = {v.x, v.y, v.z, v.w};
            #pragma unroll
            for (int q = 0; q < 4; q++) {
                unsigned u = uu[q];
                if (u >= hiT) {
                    asum += __uint_as_float(u);
                } else if ((int)(u >> 20) == b1) {
                    int bin = (u >> 8) & 0xFFF;
                    unsigned peers = __match_any_sync(__activemask(), bin);
                    if ((int)(__ffs(peers) - 1) == lane)
                        atomicAdd(&hist[bin], __popc(peers));
                }
            }
        }
        // block-reduce asum
        #pragma unroll
        for (int o = 16; o; o >>= 1) asum += __shfl_down_sync(~0u, asum, o);
        if (lane == 0) sred[wid] = asum;
        __syncthreads();
        if (wid == 0) {
            float v = (lane < 32) ? sred[lane] : 0.f;
            #pragma unroll
            for (int o = 16; o; o >>= 1) v += __shfl_down_sync(~0u, v, o);
            if (lane == 0) s_asum = v;
        }
        __syncthreads();

        // suffix scan over 4096 sub-bins, 4 bins/thread
        {
            const int K2 = K - s_cA;      // >= 1, crossing guaranteed inside b1
            int c[4], tot = 0;
            #pragma unroll
            for (int q = 0; q < 4; q++) { c[q] = hist[4095 - 4 * tid - q]; tot += c[q]; }
            int sc = tot;
            #pragma unroll
            for (int o = 1; o < 32; o <<= 1) {
                int v = __shfl_up_sync(~0u, sc, o);
                if (lane >= o) sc += v;
            }
            if (lane == 31) swsum[wid] = sc;
            __syncthreads();
            if (wid == 0) {
                int v = (lane < 32) ? swsum[lane] : 0;
                int s = v;
                #pragma unroll
                for (int o = 1; o < 32; o <<= 1) {
                    int x = __shfl_up_sync(~0u, s, o);
                    if (lane >= o) s += x;
                }
                swsum[lane] = s - v;
            }
            __syncthreads();
            int before = sc - tot + swsum[wid];
            if (before < K2 && before + tot >= K2) {    // unique owner
                int acc = before, b2 = 4095 - 4 * tid, cSA = before;
                #pragma unroll
                for (int q = 0; q < 4; q++) {
                    if (acc + c[q] >= K2) { b2 = 4095 - 4 * tid - q; cSA = acc; break; }
                    acc += c[q];
                }
                s_b2 = b2; s_need = K2 - cSA;
            }
            __syncthreads();
        }

        // selected-in-b1 portion from counts x sub-bin midpoints (err < 2^-12 rel)
        const int b2 = s_b2;
        float msum = 0.f;
        for (int i = tid; i < 4096; i += NT) {
            if (i > b2 && hist[i]) {
                float mid = __uint_as_float(((unsigned)b1 << 20) | ((unsigned)i << 8) | 0x80u);
                msum += (float)hist[i] * mid;
            }
        }
        #pragma unroll
        for (int o = 16; o; o >>= 1) msum += __shfl_down_sync(~0u, msum, o);
        if (lane == 0) sred[wid] = msum;
        __syncthreads();
        if (wid == 0) {
            float v = (lane < 32) ? sred[lane] : 0.f;
            #pragma unroll
            for (int o = 16; o; o >>= 1) v += __shfl_down_sync(~0u, v, o);
            if (lane == 0) {
                float midb2 = __uint_as_float(((unsigned)b1 << 20) | ((unsigned)b2 << 8) | 0x80u);
                s_ans = s_asum + v + (float)s_need * midb2;
            }
        }
        __syncthreads();
    }

    // ---------- accumulate + folded finalization ----------
    if (tid == 0) {
        atomicAdd(&g_acc, (double)s_ans);
        __threadfence();
        int done = atomicAdd(&g_done, 1);
        if (done == NGROUPS - 1) {
            __threadfence();
            double total = atomicAdd(&g_acc, 0.0);   // coherent read after fence
            out[0] = (float)(total * (1.0 / 64.0));
            g_acc  = 0.0;
            g_done = 0;
        }
    }
}

extern "C" void kernel_launch(void* const* d_in, const int* in_sizes, int n_in,
                              void* d_out, int out_size)
{
    // identify inputs by element count (robust to metadata ordering)
    const float *pred0 = nullptr, *pred1 = nullptr, *pred2 = nullptr, *gtb = nullptr;
    const int *gtl = nullptr;
    for (int i = 0; i < n_in; i++) {
        switch (in_sizes[i]) {
            case 25165824: pred0 = (const float*)d_in[i]; break;  // 64*24*128*128
            case 6291456:  pred1 = (const float*)d_in[i]; break;  // 64*24*64*64
            case 1572864:  pred2 = (const float*)d_in[i]; break;  // 64*24*32*32
            case 8192:     gtb   = (const float*)d_in[i]; break;  // 64*32*4
            case 2048:     gtl   = (const int*)d_in[i];   break;  // 64*32
            default: break;                                       // anchors: recomputed
        }
    }

    match_all<<<dim3(84, BATCH), 256>>>(pred0, pred1, pred2, gtb, gtl);
    select_kernel<<<NGROUPS, 1024>>>((float*)d_out);
}